// round 2
// baseline (speedup 1.0000x reference)
#include <cuda_runtime.h>
#include <math.h>

// ---- problem constants ----
#define BB    2
#define TT    4096
#define CC    1024
#define HH    16
#define HDD   64
#define WW    256
#define NWIN  16
#define MROWS (BB*TT)   // 8192

#define NEG_INF (-__int_as_float(0x7f800000))

// ---- scratch (device globals; no allocation allowed) ----
__device__ float g_q[(size_t)MROWS * CC];   // [B,H,T,HD]
__device__ float g_k[(size_t)MROWS * CC];   // [B,H,T,HD]
__device__ float g_v[(size_t)MROWS * CC];   // [B,H,T,HD]
__device__ float g_y[(size_t)MROWS * CC];   // [B,T,C]

// ============================================================
// 128x128 tile NT GEMM core: C[m,n] = sum_k A[m,k]*Bm[n,k]
// 256 threads, 8x8 per thread, BK=16, register-prefetch double buffer.
// ============================================================
__device__ __forceinline__ void gemm_tile_128(
    const float* __restrict__ A, const float* __restrict__ Bm,
    int m_base, int n_base, float acc[8][8])
{
    __shared__ float sA[16 * 128];
    __shared__ float sB[16 * 128];

    const int tid  = threadIdx.x;
    const int tx   = tid & 15;
    const int ty   = tid >> 4;
    const int lrow = tid >> 2;          // 0..63
    const int lcol = (tid & 3) << 2;    // 0,4,8,12

    const float* aP = A  + (size_t)(m_base + lrow) * CC + lcol;
    const float* bP = Bm + (size_t)(n_base + lrow) * CC + lcol;

    float4 a0 = *(const float4*)(aP);
    float4 a1 = *(const float4*)(aP + (size_t)64 * CC);
    float4 b0 = *(const float4*)(bP);
    float4 b1 = *(const float4*)(bP + (size_t)64 * CC);

    #pragma unroll
    for (int i = 0; i < 8; ++i)
        #pragma unroll
        for (int j = 0; j < 8; ++j)
            acc[i][j] = 0.0f;

    for (int kt = 0; kt < CC; kt += 16) {
        // store current tile (transposed) into smem
        sA[(lcol + 0) * 128 + lrow]      = a0.x;
        sA[(lcol + 1) * 128 + lrow]      = a0.y;
        sA[(lcol + 2) * 128 + lrow]      = a0.z;
        sA[(lcol + 3) * 128 + lrow]      = a0.w;
        sA[(lcol + 0) * 128 + lrow + 64] = a1.x;
        sA[(lcol + 1) * 128 + lrow + 64] = a1.y;
        sA[(lcol + 2) * 128 + lrow + 64] = a1.z;
        sA[(lcol + 3) * 128 + lrow + 64] = a1.w;

        sB[(lcol + 0) * 128 + lrow]      = b0.x;
        sB[(lcol + 1) * 128 + lrow]      = b0.y;
        sB[(lcol + 2) * 128 + lrow]      = b0.z;
        sB[(lcol + 3) * 128 + lrow]      = b0.w;
        sB[(lcol + 0) * 128 + lrow + 64] = b1.x;
        sB[(lcol + 1) * 128 + lrow + 64] = b1.y;
        sB[(lcol + 2) * 128 + lrow + 64] = b1.z;
        sB[(lcol + 3) * 128 + lrow + 64] = b1.w;

        __syncthreads();

        // prefetch next k-tile into registers (hidden under compute)
        if (kt + 16 < CC) {
            a0 = *(const float4*)(aP + kt + 16);
            a1 = *(const float4*)(aP + (size_t)64 * CC + kt + 16);
            b0 = *(const float4*)(bP + kt + 16);
            b1 = *(const float4*)(bP + (size_t)64 * CC + kt + 16);
        }

        #pragma unroll
        for (int kk = 0; kk < 16; ++kk) {
            float4 x0 = *(const float4*)(sA + kk * 128 + ty * 8);
            float4 x1 = *(const float4*)(sA + kk * 128 + ty * 8 + 4);
            float4 y0 = *(const float4*)(sB + kk * 128 + tx * 8);
            float4 y1 = *(const float4*)(sB + kk * 128 + tx * 8 + 4);
            float ra[8] = {x0.x, x0.y, x0.z, x0.w, x1.x, x1.y, x1.z, x1.w};
            float rb[8] = {y0.x, y0.y, y0.z, y0.w, y1.x, y1.y, y1.z, y1.w};
            #pragma unroll
            for (int i = 0; i < 8; ++i)
                #pragma unroll
                for (int j = 0; j < 8; ++j)
                    acc[i][j] = fmaf(ra[i], rb[j], acc[i][j]);
        }
        __syncthreads();
    }
}

// ============================================================
// QKV GEMM (+RoPE for q,k) -> [B,H,T,HD]
// grid: (C/128, M/128, 3)   z: 0=q(rope) 1=k(rope) 2=v
// ============================================================
__global__ void __launch_bounds__(256, 2)
qkv_kernel(const float* __restrict__ X,
           const float* __restrict__ Wq,
           const float* __restrict__ Wk,
           const float* __restrict__ Wv)
{
    const int n_base = blockIdx.x * 128;
    const int m_base = blockIdx.y * 128;
    const float* Wm = (blockIdx.z == 0) ? Wq : ((blockIdx.z == 1) ? Wk : Wv);
    float* Out      = (blockIdx.z == 0) ? g_q : ((blockIdx.z == 1) ? g_k : g_v);
    const bool rope = (blockIdx.z < 2);

    float acc[8][8];
    gemm_tile_128(X, Wm, m_base, n_base, acc);

    const int tx = threadIdx.x & 15;
    const int ty = threadIdx.x >> 4;

    #pragma unroll
    for (int i = 0; i < 8; ++i) {
        const int m = m_base + ty * 8 + i;
        const int b = m >> 12;            // m / T
        const int t = m & (TT - 1);       // m % T
        #pragma unroll
        for (int jp = 0; jp < 4; ++jp) {
            const int n = n_base + tx * 8 + jp * 2;   // even column
            float xe = acc[i][jp * 2];
            float xo = acc[i][jp * 2 + 1];
            if (rope) {
                const int d = n & (HDD - 1);          // even
                const float invf = 1.0f / powf(10000.0f, (float)d * (1.0f / 64.0f));
                float sn, cs;
                sincosf((float)t * invf, &sn, &cs);
                const float oe = xe * cs - xo * sn;
                const float oo = xe * sn + xo * cs;
                xe = oe; xo = oo;
            }
            const int h  = n >> 6;
            const int d2 = n & (HDD - 1);
            const size_t off = (((size_t)(b * HH + h) * TT + t) * HDD) + d2;
            Out[off]     = xe;
            Out[off + 1] = xo;
        }
    }
}

// ============================================================
// Output projection GEMM: d_out = Y @ Wo^T   (row-major [B*T, C])
// grid: (C/128, M/128)
// ============================================================
__global__ void __launch_bounds__(256, 2)
out_kernel(const float* __restrict__ Wo, float* __restrict__ Out)
{
    const int n_base = blockIdx.x * 128;
    const int m_base = blockIdx.y * 128;

    float acc[8][8];
    gemm_tile_128(g_y, Wo, m_base, n_base, acc);

    const int tx = threadIdx.x & 15;
    const int ty = threadIdx.x >> 4;

    #pragma unroll
    for (int i = 0; i < 8; ++i) {
        const int m = m_base + ty * 8 + i;
        float* p = Out + (size_t)m * CC + n_base + tx * 8;
        *(float4*)(p)     = make_float4(acc[i][0], acc[i][1], acc[i][2], acc[i][3]);
        *(float4*)(p + 4) = make_float4(acc[i][4], acc[i][5], acc[i][6], acc[i][7]);
    }
}

// ============================================================
// Fused windowed attention.
// One CTA = (b,h,window, 64-row q chunk). 256 threads.
// smem: Qt[64][64] (k-major), Kt[64][256] (k-major), Vs[256][64], S[64][260]
// ============================================================
#define S_STRIDE 260
#define ATTN_SMEM_FLOATS (64*64 + 64*256 + 256*64 + 64*S_STRIDE)
#define ATTN_SMEM_BYTES  (ATTN_SMEM_FLOATS * 4)

__global__ void __launch_bounds__(256, 1)
attn_kernel()
{
    extern __shared__ float sm[];
    float* Qt = sm;                       // [64 kd][64 q]
    float* Kt = sm + 64 * 64;             // [64 kd][256 kj]
    float* Vs = Kt + 64 * 256;            // [256 kj][64 d]
    float* S  = Vs + 256 * 64;            // [64 q][260]

    const int tid = threadIdx.x;
    const int bx  = blockIdx.x;
    const int qc  = bx & 3;               // q chunk within window
    const int w   = (bx >> 2) & (NWIN - 1);
    const int bh  = bx >> 6;              // 0..31
    const int b   = bh >> 4;
    const int h   = bh & (HH - 1);

    const float* qptr = g_q + ((size_t)bh * TT + w * WW + qc * 64) * HDD;
    const float* kptr = g_k + ((size_t)bh * TT + w * WW) * HDD;
    const float* vptr = g_v + ((size_t)bh * TT + w * WW) * HDD;

    // ---- load Q (transposed), K (transposed), V ----
    #pragma unroll
    for (int i = 0; i < 4; ++i) {
        const int f   = tid + i * 256;    // 0..1023 float4s of Q
        const int row = f >> 4;           // 0..63
        const int cg  = (f & 15) * 4;
        float4 v = *(const float4*)(qptr + row * HDD + cg);
        Qt[(cg + 0) * 64 + row] = v.x;
        Qt[(cg + 1) * 64 + row] = v.y;
        Qt[(cg + 2) * 64 + row] = v.z;
        Qt[(cg + 3) * 64 + row] = v.w;
    }
    #pragma unroll
    for (int i = 0; i < 16; ++i) {
        const int f   = tid + i * 256;    // 0..4095 float4s of K
        const int row = f >> 4;           // 0..255
        const int cg  = (f & 15) * 4;
        float4 v = *(const float4*)(kptr + row * HDD + cg);
        Kt[(cg + 0) * 256 + row] = v.x;
        Kt[(cg + 1) * 256 + row] = v.y;
        Kt[(cg + 2) * 256 + row] = v.z;
        Kt[(cg + 3) * 256 + row] = v.w;
    }
    #pragma unroll
    for (int i = 0; i < 16; ++i) {
        const int f = tid + i * 256;
        ((float4*)Vs)[f] = ((const float4*)vptr)[f];
    }
    __syncthreads();

    // ---- S = Q K^T * scale : 8x8 per thread over [64 q][256 kj] ----
    {
        const int ti = tid >> 5;          // 0..7  -> q block
        const int tj = tid & 31;          // 0..31 -> kj block
        float acc[8][8];
        #pragma unroll
        for (int i = 0; i < 8; ++i)
            #pragma unroll
            for (int j = 0; j < 8; ++j)
                acc[i][j] = 0.0f;

        #pragma unroll 4
        for (int kk = 0; kk < 64; ++kk) {
            float4 a0 = *(const float4*)(Qt + kk * 64 + ti * 8);
            float4 a1 = *(const float4*)(Qt + kk * 64 + ti * 8 + 4);
            float4 b0 = *(const float4*)(Kt + kk * 256 + tj * 8);
            float4 b1 = *(const float4*)(Kt + kk * 256 + tj * 8 + 4);
            float ra[8] = {a0.x, a0.y, a0.z, a0.w, a1.x, a1.y, a1.z, a1.w};
            float rb[8] = {b0.x, b0.y, b0.z, b0.w, b1.x, b1.y, b1.z, b1.w};
            #pragma unroll
            for (int i = 0; i < 8; ++i)
                #pragma unroll
                for (int j = 0; j < 8; ++j)
                    acc[i][j] = fmaf(ra[i], rb[j], acc[i][j]);
        }

        const float scale = 0.125f;       // 1/sqrt(64)
        #pragma unroll
        for (int i = 0; i < 8; ++i) {
            const int q = ti * 8 + i;
            #pragma unroll
            for (int j = 0; j < 8; ++j)
                S[q * S_STRIDE + tj * 8 + j] = acc[i][j] * scale;
        }
    }
    __syncthreads();

    // ---- row softmax: 4 threads per row, 64 elements each ----
    {
        const int row  = tid >> 2;        // 0..63
        const int part = tid & 3;
        float4* rp4 = (float4*)(S + row * S_STRIDE + part * 64);

        float mx = NEG_INF;
        #pragma unroll
        for (int j = 0; j < 16; ++j) {
            float4 v = rp4[j];
            mx = fmaxf(mx, fmaxf(fmaxf(v.x, v.y), fmaxf(v.z, v.w)));
        }
        mx = fmaxf(mx, __shfl_xor_sync(0xffffffffu, mx, 1));
        mx = fmaxf(mx, __shfl_xor_sync(0xffffffffu, mx, 2));

        float l = 0.0f;
        #pragma unroll
        for (int j = 0; j < 16; ++j) {
            float4 v = rp4[j];
            v.x = expf(v.x - mx);
            v.y = expf(v.y - mx);
            v.z = expf(v.z - mx);
            v.w = expf(v.w - mx);
            l += v.x + v.y + v.z + v.w;
            rp4[j] = v;
        }
        l += __shfl_xor_sync(0xffffffffu, l, 1);
        l += __shfl_xor_sync(0xffffffffu, l, 2);
        const float inv = 1.0f / l;
        #pragma unroll
        for (int j = 0; j < 16; ++j) {
            float4 v = rp4[j];
            v.x *= inv; v.y *= inv; v.z *= inv; v.w *= inv;
            rp4[j] = v;
        }
    }
    __syncthreads();

    // ---- Y = P V : 4x4 per thread over [64 q][64 d] ----
    {
        const int qg = tid >> 4;          // 0..15 -> q_base = qg*4
        const int dg = tid & 15;          // 0..15 -> d_base = dg*4
        const int q_base = qg * 4;
        const int d_base = dg * 4;

        float acc[4][4];
        #pragma unroll
        for (int i = 0; i < 4; ++i)
            #pragma unroll
            for (int j = 0; j < 4; ++j)
                acc[i][j] = 0.0f;

        #pragma unroll 4
        for (int kk = 0; kk < 256; ++kk) {
            float4 v = *(const float4*)(Vs + kk * HDD + d_base);
            #pragma unroll
            for (int i = 0; i < 4; ++i) {
                const float s = S[(q_base + i) * S_STRIDE + kk];
                acc[i][0] = fmaf(s, v.x, acc[i][0]);
                acc[i][1] = fmaf(s, v.y, acc[i][1]);
                acc[i][2] = fmaf(s, v.z, acc[i][2]);
                acc[i][3] = fmaf(s, v.w, acc[i][3]);
            }
        }

        // write Y in [B,T,C] layout
        #pragma unroll
        for (int i = 0; i < 4; ++i) {
            const int t_global = w * WW + qc * 64 + q_base + i;
            float* p = g_y + ((size_t)b * TT + t_global) * CC + h * HDD + d_base;
            *(float4*)p = make_float4(acc[i][0], acc[i][1], acc[i][2], acc[i][3]);
        }
    }
}

// ============================================================
// launcher
// ============================================================
extern "C" void kernel_launch(void* const* d_in, const int* in_sizes, int n_in,
                              void* d_out, int out_size)
{
    (void)in_sizes; (void)n_in; (void)out_size;
    const float* x  = (const float*)d_in[0];
    const float* wq = (const float*)d_in[1];
    const float* wk = (const float*)d_in[2];
    const float* wv = (const float*)d_in[3];
    const float* wo = (const float*)d_in[4];
    float* out = (float*)d_out;

    cudaFuncSetAttribute(attn_kernel,
                         cudaFuncAttributeMaxDynamicSharedMemorySize,
                         ATTN_SMEM_BYTES);

    dim3 g1(CC / 128, MROWS / 128, 3);
    qkv_kernel<<<g1, 256>>>(x, wq, wk, wv);

    attn_kernel<<<BB * HH * NWIN * (WW / 64), 256, ATTN_SMEM_BYTES>>>();

    dim3 g2(CC / 128, MROWS / 128);
    out_kernel<<<g2, 256>>>(wo, out);
}

// round 7
// speedup vs baseline: 2.1586x; 2.1586x over previous
#include <cuda_runtime.h>
#include <cuda_bf16.h>
#include <math.h>
#include <stdint.h>

// ---- problem constants ----
#define BB    2
#define TT    4096
#define CC    1024
#define HH    16
#define HDD   64
#define WW    256
#define NWIN  16
#define MROWS (BB*TT)   // 8192

#define NEG_INF (-__int_as_float(0x7f800000))

// ---- mma GEMM tiling ----
#define BKk       64
#define NCHUNK    (CC/BKk)     // 16
#define STG_BYTES 65536        // Ah16K + Al16K + Bh16K + Bl16K
#define NSTG      3
#define GEMM_SMEM (NSTG*STG_BYTES)   // 196608

// ---- scratch (device globals; no allocation allowed) ----
__device__ __nv_bfloat16 g_xh[(size_t)MROWS * CC];
__device__ __nv_bfloat16 g_xl[(size_t)MROWS * CC];
__device__ __nv_bfloat16 g_wh[4][(size_t)CC * CC];   // 0=wq 1=wk 2=wv 3=wo
__device__ __nv_bfloat16 g_wl[4][(size_t)CC * CC];
__device__ __nv_bfloat16 g_yh[(size_t)MROWS * CC];   // [B,T,C]
__device__ __nv_bfloat16 g_yl[(size_t)MROWS * CC];
__device__ float  g_q[(size_t)MROWS * CC];           // [B,H,T,HD]
__device__ float  g_k[(size_t)MROWS * CC];
__device__ float  g_v[(size_t)MROWS * CC];
__device__ float2 g_rope[(size_t)TT * 32];           // (cos,sin) per (t,i)

// ============================================================
// PTX helpers (base sm_103 ISA only: mma.sync / ldmatrix / cp.async)
// ============================================================
__device__ __forceinline__ uint32_t smem_u32(const void* p) {
    uint32_t a;
    asm("{ .reg .u64 t; cvta.to.shared.u64 t, %1; cvt.u32.u64 %0, t; }" : "=r"(a) : "l"(p));
    return a;
}

// pack two floats -> bf16x2 (lo arg in low half)
__device__ __forceinline__ uint32_t bf16x2(float lo, float hi) {
    uint32_t r;
    asm("cvt.rn.satfinite.bf16x2.f32 %0, %1, %2;" : "=r"(r) : "f"(hi), "f"(lo));
    return r;
}

#define CP16(saddr, gptr) \
    asm volatile("cp.async.cg.shared.global [%0], [%1], 16;" \
                 :: "r"(saddr), "l"(gptr) : "memory")
#define CP_COMMIT() asm volatile("cp.async.commit_group;" ::: "memory")
#define CP_WAIT2()  asm volatile("cp.async.wait_group 2;"  ::: "memory")

#define LDSM4(r, addr) \
    asm volatile("ldmatrix.sync.aligned.m8n8.x4.shared.b16 {%0,%1,%2,%3}, [%4];" \
                 : "=r"((r)[0]), "=r"((r)[1]), "=r"((r)[2]), "=r"((r)[3]) : "r"(addr))

#define MMA16816(d, a, b0, b1) \
    asm volatile("mma.sync.aligned.m16n8k16.row.col.f32.bf16.bf16.f32 " \
                 "{%0,%1,%2,%3}, {%4,%5,%6,%7}, {%8,%9}, {%0,%1,%2,%3};" \
                 : "+f"((d)[0]), "+f"((d)[1]), "+f"((d)[2]), "+f"((d)[3]) \
                 : "r"((a)[0]), "r"((a)[1]), "r"((a)[2]), "r"((a)[3]), \
                   "r"(b0), "r"(b1))

// ============================================================
// split-bf16 NT GEMM mainloop: acc += A[TM=128,K]*B[TN=128,K]^T, K=1024
// A,B given as bf16 hi/lo pairs. 256 threads, 8 warps (4m x 2n),
// warp tile 32x64, 3-stage cp.async pipeline, SW-swizzled smem.
// ============================================================
__device__ __forceinline__ void mma_mainloop(
    const __nv_bfloat16* __restrict__ Ah, const __nv_bfloat16* __restrict__ Al,
    const __nv_bfloat16* __restrict__ Bh, const __nv_bfloat16* __restrict__ Bl,
    int m_base, int n_base, char* sm, float acc[2][8][4])
{
    const int tid  = threadIdx.x;
    const int lane = tid & 31;
    const int wid  = tid >> 5;
    const int wm   = wid & 3;      // warp m: 32 rows
    const int wn   = wid >> 2;     // warp n: 64 cols
    const uint32_t sb = smem_u32(sm);

    // cp.async per-thread offsets: 4 x 16B segments per matrix per stage.
    // seg = tid + i*256; row = seg>>3 (0..127); kseg = seg&7 (16B within 128B row)
    uint32_t s_off[4];
    size_t   g_off[4];
    #pragma unroll
    for (int i = 0; i < 4; ++i) {
        const int seg = tid + i * 256;
        const int row = seg >> 3, ks = seg & 7;
        s_off[i] = (uint32_t)(row * 128 + ((ks ^ (row & 7)) << 4));
        g_off[i] = (size_t)row * CC + (size_t)ks * 8;
    }
    const __nv_bfloat16* Ahb = Ah + (size_t)m_base * CC;
    const __nv_bfloat16* Alb = Al + (size_t)m_base * CC;
    const __nv_bfloat16* Bhb = Bh + (size_t)n_base * CC;
    const __nv_bfloat16* Blb = Bl + (size_t)n_base * CC;

    auto issue_stage = [&](int kt) {
        const uint32_t st = sb + (uint32_t)(kt % NSTG) * STG_BYTES;
        const size_t ko = (size_t)kt * BKk;
        #pragma unroll
        for (int i = 0; i < 4; ++i) {
            CP16(st +          s_off[i], Ahb + g_off[i] + ko);
            CP16(st + 16384u + s_off[i], Alb + g_off[i] + ko);
            CP16(st + 32768u + s_off[i], Bhb + g_off[i] + ko);
            CP16(st + 49152u + s_off[i], Blb + g_off[i] + ko);
        }
    };

    // ldmatrix per-warp address components
    const int a_row    = wm * 32 + (lane & 7) + ((lane >> 3) & 1) * 8;
    const int a_khalf  = (lane >> 4) & 1;                 // +8 k elems
    const int b_row    = wn * 64 + (lane & 7) + ((lane >> 4) & 1) * 8;
    const int b_khalf  = (lane >> 3) & 1;

    uint32_t arow_b[2]; int arow_7[2];
    #pragma unroll
    for (int mf = 0; mf < 2; ++mf) {
        const int r = a_row + mf * 16;
        arow_b[mf] = (uint32_t)(r * 128);
        arow_7[mf] = r & 7;
    }
    uint32_t brow_b[4]; int brow_7[4];
    #pragma unroll
    for (int nf2 = 0; nf2 < 4; ++nf2) {
        const int r = b_row + nf2 * 16;
        brow_b[nf2] = (uint32_t)(r * 128);
        brow_7[nf2] = r & 7;
    }

    // prologue: fill 3 stages
    #pragma unroll
    for (int s = 0; s < NSTG; ++s) { issue_stage(s); CP_COMMIT(); }

    for (int kt = 0; kt < NCHUNK; ++kt) {
        CP_WAIT2();
        __syncthreads();

        const uint32_t st = sb + (uint32_t)(kt % NSTG) * STG_BYTES;

        #pragma unroll
        for (int ks = 0; ks < 4; ++ks) {
            uint32_t ah[2][4], al[2][4], bh[4][4], bl[4][4];
            #pragma unroll
            for (int mf = 0; mf < 2; ++mf) {
                const uint32_t ad = st + arow_b[mf] +
                    (uint32_t)((((ks << 1) | a_khalf) ^ arow_7[mf]) << 4);
                LDSM4(ah[mf], ad);
                LDSM4(al[mf], ad + 16384u);
            }
            #pragma unroll
            for (int nf2 = 0; nf2 < 4; ++nf2) {
                const uint32_t bd = st + 32768u + brow_b[nf2] +
                    (uint32_t)((((ks << 1) | b_khalf) ^ brow_7[nf2]) << 4);
                LDSM4(bh[nf2], bd);
                LDSM4(bl[nf2], bd + 16384u);
            }
            #pragma unroll
            for (int mf = 0; mf < 2; ++mf)
                #pragma unroll
                for (int nf = 0; nf < 8; ++nf) {
                    const int j2 = nf >> 1, jo = (nf & 1) * 2;
                    MMA16816(acc[mf][nf], ah[mf], bh[j2][jo], bh[j2][jo + 1]);
                    MMA16816(acc[mf][nf], ah[mf], bl[j2][jo], bl[j2][jo + 1]);
                    MMA16816(acc[mf][nf], al[mf], bh[j2][jo], bh[j2][jo + 1]);
                }
        }

        __syncthreads();
        if (kt + NSTG < NCHUNK) issue_stage(kt + NSTG);
        CP_COMMIT();
    }
}

// ============================================================
// convert fp32 -> bf16 hi/lo scratch.  which: 0=X, 1..4=weights
// ============================================================
__global__ void cvt_kernel(const float* __restrict__ src, int which, int n4)
{
    const int i = blockIdx.x * 256 + threadIdx.x;
    if (i >= n4) return;
    const float4 v = ((const float4*)src)[i];
    __nv_bfloat16 *dh, *dl;
    if (which == 0) { dh = g_xh; dl = g_xl; }
    else            { dh = g_wh[which - 1]; dl = g_wl[which - 1]; }

    const uint32_t h01 = bf16x2(v.x, v.y);
    const uint32_t h23 = bf16x2(v.z, v.w);
    const float f0 = __uint_as_float(h01 << 16);
    const float f1 = __uint_as_float(h01 & 0xffff0000u);
    const float f2 = __uint_as_float(h23 << 16);
    const float f3 = __uint_as_float(h23 & 0xffff0000u);
    const uint32_t l01 = bf16x2(v.x - f0, v.y - f1);
    const uint32_t l23 = bf16x2(v.z - f2, v.w - f3);
    ((uint2*)dh)[i] = make_uint2(h01, h23);
    ((uint2*)dl)[i] = make_uint2(l01, l23);
}

// ============================================================
// rope table: g_rope[t*32+i] = (cos, sin)(t * 10000^(-2i/64))
// ============================================================
__global__ void rope_table_kernel()
{
    const int idx = blockIdx.x * 256 + threadIdx.x;   // 0 .. 4096*32-1
    const int t = idx >> 5, i = idx & 31;
    const float invf = powf(10000.0f, -(float)(2 * i) * (1.0f / 64.0f));
    float s, c;
    sincosf((float)t * invf, &s, &c);
    g_rope[idx] = make_float2(c, s);
}

// ============================================================
// QKV projection (+RoPE) -> [B,H,T,HD].  grid (8, 64, 3), 256 thr
// ============================================================
__global__ void __launch_bounds__(256, 1)
qkv_mma_kernel()
{
    extern __shared__ char sm[];
    const int n_base = blockIdx.x * 128;
    const int m_base = blockIdx.y * 128;
    const int z = blockIdx.z;
    float* Out = (z == 0) ? g_q : ((z == 1) ? g_k : g_v);
    const bool rope = (z < 2);

    float acc[2][8][4];
    #pragma unroll
    for (int a = 0; a < 2; ++a)
        #pragma unroll
        for (int b = 0; b < 8; ++b)
            #pragma unroll
            for (int c = 0; c < 4; ++c) acc[a][b][c] = 0.0f;

    mma_mainloop(g_xh, g_xl, g_wh[z], g_wl[z], m_base, n_base, sm, acc);

    const int lane = threadIdx.x & 31, wid = threadIdx.x >> 5;
    const int wm = wid & 3, wn = wid >> 2;
    const int mrow0 = m_base + wm * 32 + (lane >> 2);
    const int ncol0 = n_base + wn * 64 + ((lane & 3) << 1);

    #pragma unroll
    for (int mf = 0; mf < 2; ++mf)
        #pragma unroll
        for (int half = 0; half < 2; ++half) {
            const int m = mrow0 + mf * 16 + half * 8;
            const int b = m >> 12, t = m & (TT - 1);
            #pragma unroll
            for (int nf = 0; nf < 8; ++nf) {
                const int nn = ncol0 + nf * 8;
                const int h = nn >> 6, d = nn & 63;
                float c0 = acc[mf][nf][half * 2];
                float c1 = acc[mf][nf][half * 2 + 1];
                if (rope) {
                    const float2 cs = g_rope[(size_t)t * 32 + (d >> 1)];
                    const float o0 = c0 * cs.x - c1 * cs.y;
                    const float o1 = c0 * cs.y + c1 * cs.x;
                    c0 = o0; c1 = o1;
                }
                *(float2*)(Out + (((size_t)(b * HH + h) * TT + t) * HDD) + d)
                    = make_float2(c0, c1);
            }
        }
}

// ============================================================
// Output projection: d_out = Y @ Wo^T.  grid (8, 64), 256 thr
// ============================================================
__global__ void __launch_bounds__(256, 1)
out_mma_kernel(float* __restrict__ Out)
{
    extern __shared__ char sm[];
    const int n_base = blockIdx.x * 128;
    const int m_base = blockIdx.y * 128;

    float acc[2][8][4];
    #pragma unroll
    for (int a = 0; a < 2; ++a)
        #pragma unroll
        for (int b = 0; b < 8; ++b)
            #pragma unroll
            for (int c = 0; c < 4; ++c) acc[a][b][c] = 0.0f;

    mma_mainloop(g_yh, g_yl, g_wh[3], g_wl[3], m_base, n_base, sm, acc);

    const int lane = threadIdx.x & 31, wid = threadIdx.x >> 5;
    const int wm = wid & 3, wn = wid >> 2;
    const int mrow0 = m_base + wm * 32 + (lane >> 2);
    const int ncol0 = n_base + wn * 64 + ((lane & 3) << 1);

    #pragma unroll
    for (int mf = 0; mf < 2; ++mf)
        #pragma unroll
        for (int half = 0; half < 2; ++half) {
            const int m = mrow0 + mf * 16 + half * 8;
            #pragma unroll
            for (int nf = 0; nf < 8; ++nf) {
                const int nn = ncol0 + nf * 8;
                *(float2*)(Out + (size_t)m * CC + nn)
                    = make_float2(acc[mf][nf][half * 2], acc[mf][nf][half * 2 + 1]);
            }
        }
}

// ============================================================
// Fused windowed attention (fp32), epilogue emits Y as bf16 hi/lo.
// One CTA = (b,h,window, 64-row q chunk). 256 threads.
// ============================================================
#define S_STRIDE 260
#define ATTN_SMEM_FLOATS (64*64 + 64*256 + 256*64 + 64*S_STRIDE)
#define ATTN_SMEM_BYTES  (ATTN_SMEM_FLOATS * 4)

__global__ void __launch_bounds__(256, 1)
attn_kernel()
{
    extern __shared__ float smf[];
    float* Qt = smf;                      // [64 kd][64 q]
    float* Kt = smf + 64 * 64;            // [64 kd][256 kj]
    float* Vs = Kt + 64 * 256;            // [256 kj][64 d]
    float* S  = Vs + 256 * 64;            // [64 q][260]

    const int tid = threadIdx.x;
    const int bx  = blockIdx.x;
    const int qc  = bx & 3;
    const int w   = (bx >> 2) & (NWIN - 1);
    const int bh  = bx >> 6;
    const int b   = bh >> 4;
    const int h   = bh & (HH - 1);

    const float* qptr = g_q + ((size_t)bh * TT + w * WW + qc * 64) * HDD;
    const float* kptr = g_k + ((size_t)bh * TT + w * WW) * HDD;
    const float* vptr = g_v + ((size_t)bh * TT + w * WW) * HDD;

    #pragma unroll
    for (int i = 0; i < 4; ++i) {
        const int f   = tid + i * 256;
        const int row = f >> 4;
        const int cg  = (f & 15) * 4;
        float4 v = *(const float4*)(qptr + row * HDD + cg);
        Qt[(cg + 0) * 64 + row] = v.x;
        Qt[(cg + 1) * 64 + row] = v.y;
        Qt[(cg + 2) * 64 + row] = v.z;
        Qt[(cg + 3) * 64 + row] = v.w;
    }
    #pragma unroll
    for (int i = 0; i < 16; ++i) {
        const int f   = tid + i * 256;
        const int row = f >> 4;
        const int cg  = (f & 15) * 4;
        float4 v = *(const float4*)(kptr + row * HDD + cg);
        Kt[(cg + 0) * 256 + row] = v.x;
        Kt[(cg + 1) * 256 + row] = v.y;
        Kt[(cg + 2) * 256 + row] = v.z;
        Kt[(cg + 3) * 256 + row] = v.w;
    }
    #pragma unroll
    for (int i = 0; i < 16; ++i) {
        const int f = tid + i * 256;
        ((float4*)Vs)[f] = ((const float4*)vptr)[f];
    }
    __syncthreads();

    {
        const int ti = tid >> 5;
        const int tj = tid & 31;
        float acc[8][8];
        #pragma unroll
        for (int i = 0; i < 8; ++i)
            #pragma unroll
            for (int j = 0; j < 8; ++j)
                acc[i][j] = 0.0f;

        #pragma unroll 4
        for (int kk = 0; kk < 64; ++kk) {
            float4 a0 = *(const float4*)(Qt + kk * 64 + ti * 8);
            float4 a1 = *(const float4*)(Qt + kk * 64 + ti * 8 + 4);
            float4 b0 = *(const float4*)(Kt + kk * 256 + tj * 8);
            float4 b1 = *(const float4*)(Kt + kk * 256 + tj * 8 + 4);
            float ra[8] = {a0.x, a0.y, a0.z, a0.w, a1.x, a1.y, a1.z, a1.w};
            float rb[8] = {b0.x, b0.y, b0.z, b0.w, b1.x, b1.y, b1.z, b1.w};
            #pragma unroll
            for (int i = 0; i < 8; ++i)
                #pragma unroll
                for (int j = 0; j < 8; ++j)
                    acc[i][j] = fmaf(ra[i], rb[j], acc[i][j]);
        }

        const float scale = 0.125f;
        #pragma unroll
        for (int i = 0; i < 8; ++i) {
            const int q = ti * 8 + i;
            #pragma unroll
            for (int j = 0; j < 8; ++j)
                S[q * S_STRIDE + tj * 8 + j] = acc[i][j] * scale;
        }
    }
    __syncthreads();

    {
        const int row  = tid >> 2;
        const int part = tid & 3;
        float4* rp4 = (float4*)(S + row * S_STRIDE + part * 64);

        float mx = NEG_INF;
        #pragma unroll
        for (int j = 0; j < 16; ++j) {
            float4 v = rp4[j];
            mx = fmaxf(mx, fmaxf(fmaxf(v.x, v.y), fmaxf(v.z, v.w)));
        }
        mx = fmaxf(mx, __shfl_xor_sync(0xffffffffu, mx, 1));
        mx = fmaxf(mx, __shfl_xor_sync(0xffffffffu, mx, 2));

        float l = 0.0f;
        #pragma unroll
        for (int j = 0; j < 16; ++j) {
            float4 v = rp4[j];
            v.x = expf(v.x - mx);
            v.y = expf(v.y - mx);
            v.z = expf(v.z - mx);
            v.w = expf(v.w - mx);
            l += v.x + v.y + v.z + v.w;
            rp4[j] = v;
        }
        l += __shfl_xor_sync(0xffffffffu, l, 1);
        l += __shfl_xor_sync(0xffffffffu, l, 2);
        const float inv = 1.0f / l;
        #pragma unroll
        for (int j = 0; j < 16; ++j) {
            float4 v = rp4[j];
            v.x *= inv; v.y *= inv; v.z *= inv; v.w *= inv;
            rp4[j] = v;
        }
    }
    __syncthreads();

    {
        const int qg = tid >> 4;
        const int dg = tid & 15;
        const int q_base = qg * 4;
        const int d_base = dg * 4;

        float acc[4][4];
        #pragma unroll
        for (int i = 0; i < 4; ++i)
            #pragma unroll
            for (int j = 0; j < 4; ++j)
                acc[i][j] = 0.0f;

        #pragma unroll 4
        for (int kk = 0; kk < 256; ++kk) {
            float4 v = *(const float4*)(Vs + kk * HDD + d_base);
            #pragma unroll
            for (int i = 0; i < 4; ++i) {
                const float s = S[(q_base + i) * S_STRIDE + kk];
                acc[i][0] = fmaf(s, v.x, acc[i][0]);
                acc[i][1] = fmaf(s, v.y, acc[i][1]);
                acc[i][2] = fmaf(s, v.z, acc[i][2]);
                acc[i][3] = fmaf(s, v.w, acc[i][3]);
            }
        }

        // write Y as bf16 hi/lo in [B,T,C] layout
        #pragma unroll
        for (int i = 0; i < 4; ++i) {
            const int t_global = w * WW + qc * 64 + q_base + i;
            const size_t off = ((size_t)b * TT + t_global) * CC + h * HDD + d_base;
            const uint32_t h01 = bf16x2(acc[i][0], acc[i][1]);
            const uint32_t h23 = bf16x2(acc[i][2], acc[i][3]);
            const float f0 = __uint_as_float(h01 << 16);
            const float f1 = __uint_as_float(h01 & 0xffff0000u);
            const float f2 = __uint_as_float(h23 << 16);
            const float f3 = __uint_as_float(h23 & 0xffff0000u);
            const uint32_t l01 = bf16x2(acc[i][0] - f0, acc[i][1] - f1);
            const uint32_t l23 = bf16x2(acc[i][2] - f2, acc[i][3] - f3);
            *(uint2*)(g_yh + off) = make_uint2(h01, h23);
            *(uint2*)(g_yl + off) = make_uint2(l01, l23);
        }
    }
}

// ============================================================
// launcher
// ============================================================
extern "C" void kernel_launch(void* const* d_in, const int* in_sizes, int n_in,
                              void* d_out, int out_size)
{
    (void)in_sizes; (void)n_in; (void)out_size;
    const float* x  = (const float*)d_in[0];
    const float* wq = (const float*)d_in[1];
    const float* wk = (const float*)d_in[2];
    const float* wv = (const float*)d_in[3];
    const float* wo = (const float*)d_in[4];
    float* out = (float*)d_out;

    cudaFuncSetAttribute(qkv_mma_kernel,
                         cudaFuncAttributeMaxDynamicSharedMemorySize, GEMM_SMEM);
    cudaFuncSetAttribute(out_mma_kernel,
                         cudaFuncAttributeMaxDynamicSharedMemorySize, GEMM_SMEM);
    cudaFuncSetAttribute(attn_kernel,
                         cudaFuncAttributeMaxDynamicSharedMemorySize, ATTN_SMEM_BYTES);

    rope_table_kernel<<<(TT * 32) / 256, 256>>>();

    const int n4x = MROWS * CC / 4;      // 2M float4
    const int n4w = CC * CC / 4;         // 256K float4
    cvt_kernel<<<(n4x + 255) / 256, 256>>>(x,  0, n4x);
    cvt_kernel<<<(n4w + 255) / 256, 256>>>(wq, 1, n4w);
    cvt_kernel<<<(n4w + 255) / 256, 256>>>(wk, 2, n4w);
    cvt_kernel<<<(n4w + 255) / 256, 256>>>(wv, 3, n4w);
    cvt_kernel<<<(n4w + 255) / 256, 256>>>(wo, 4, n4w);

    dim3 g1(CC / 128, MROWS / 128, 3);
    qkv_mma_kernel<<<g1, 256, GEMM_SMEM>>>();

    attn_kernel<<<BB * HH * NWIN * (WW / 64), 256, ATTN_SMEM_BYTES>>>();

    dim3 g2(CC / 128, MROWS / 128);
    out_mma_kernel<<<g2, 256, GEMM_SMEM>>>(out);
}